// round 1
// baseline (speedup 1.0000x reference)
#include <cuda_runtime.h>
#include <cuda_bf16.h>
#include <cstddef>

// Problem constants
#define BB 4
#define SS 4096
#define DD 1024
#define HH 16
#define DK 64
#define MM (BB * SS)          // 16384

// ---------------- scratch (device globals; no runtime allocation) ----------
__device__ float g_Q[(size_t)MM * DD];
__device__ float g_K[(size_t)MM * DD];
__device__ float g_V[(size_t)MM * DD];
__device__ float g_A[(size_t)MM * DD];

#define KV_SPLIT 8
__device__ float g_KVp[(size_t)KV_SPLIT * 64 * DK * DK];
__device__ float g_KSp[(size_t)KV_SPLIT * 64 * DK];
__device__ float g_KV[(size_t)64 * DK * DK];
__device__ float g_KS[(size_t)64 * DK];

// ---------------- GEMM: C[m,n] = sum_k A[m,k] * W[n,k]  (both K-major) -----
// mode: 0 = plain, 1 = phi (elu+1), 2 = +bias
#define BM 128
#define BN 128
#define BKK 16
#define SST 132   // shared row stride (16B-aligned, reduces store conflicts)

__global__ void __launch_bounds__(256, 2)
gemm_nt(const float* __restrict__ A, const float* __restrict__ W,
        const float* __restrict__ bias, float* __restrict__ C,
        int M, int N, int K, int mode)
{
    __shared__ float As[BKK][SST];
    __shared__ float Bs[BKK][SST];

    const int tid = threadIdx.x;
    const int tx = tid & 15;         // 0..15 -> n micro-tile
    const int ty = tid >> 4;         // 0..15 -> m micro-tile
    const int bm = blockIdx.y * BM;
    const int bn = blockIdx.x * BN;

    const int lm = tid >> 2;         // 0..63 load row
    const int lk = (tid & 3) * 4;    // 0,4,8,12 load k

    const float* Aptr = A + (size_t)(bm + lm) * K + lk;
    const float* Wptr = W + (size_t)(bn + lm) * K + lk;

    float acc[8][8];
#pragma unroll
    for (int i = 0; i < 8; i++)
#pragma unroll
        for (int j = 0; j < 8; j++) acc[i][j] = 0.0f;

    for (int k0 = 0; k0 < K; k0 += BKK) {
        float4 a0 = *(const float4*)(Aptr);
        float4 a1 = *(const float4*)(Aptr + (size_t)64 * K);
        float4 b0 = *(const float4*)(Wptr);
        float4 b1 = *(const float4*)(Wptr + (size_t)64 * K);

        As[lk + 0][lm] = a0.x; As[lk + 1][lm] = a0.y;
        As[lk + 2][lm] = a0.z; As[lk + 3][lm] = a0.w;
        As[lk + 0][lm + 64] = a1.x; As[lk + 1][lm + 64] = a1.y;
        As[lk + 2][lm + 64] = a1.z; As[lk + 3][lm + 64] = a1.w;
        Bs[lk + 0][lm] = b0.x; Bs[lk + 1][lm] = b0.y;
        Bs[lk + 2][lm] = b0.z; Bs[lk + 3][lm] = b0.w;
        Bs[lk + 0][lm + 64] = b1.x; Bs[lk + 1][lm + 64] = b1.y;
        Bs[lk + 2][lm + 64] = b1.z; Bs[lk + 3][lm + 64] = b1.w;

        __syncthreads();

#pragma unroll
        for (int kk = 0; kk < BKK; kk++) {
            float a[8], b[8];
            *(float4*)(a)     = *(const float4*)&As[kk][ty * 8];
            *(float4*)(a + 4) = *(const float4*)&As[kk][ty * 8 + 4];
            *(float4*)(b)     = *(const float4*)&Bs[kk][tx * 8];
            *(float4*)(b + 4) = *(const float4*)&Bs[kk][tx * 8 + 4];
#pragma unroll
            for (int i = 0; i < 8; i++)
#pragma unroll
                for (int j = 0; j < 8; j++)
                    acc[i][j] += a[i] * b[j];
        }
        __syncthreads();

        Aptr += BKK;
        Wptr += BKK;
    }

    // epilogue
#pragma unroll
    for (int i = 0; i < 8; i++) {
        const int m = bm + ty * 8 + i;
        float* crow = C + (size_t)m * N + bn + tx * 8;
#pragma unroll
        for (int j4 = 0; j4 < 2; j4++) {
            float4 v4;
            float tmp[4];
#pragma unroll
            for (int j = 0; j < 4; j++) {
                float v = acc[i][j4 * 4 + j];
                if (mode == 1) v = (v > 0.0f) ? (v + 1.0f) : expf(v);
                else if (mode == 2) v += bias[bn + tx * 8 + j4 * 4 + j];
                tmp[j] = v;
            }
            v4.x = tmp[0]; v4.y = tmp[1]; v4.z = tmp[2]; v4.w = tmp[3];
            *(float4*)(crow + j4 * 4) = v4;
        }
    }
}

// ---------------- KV accumulation: KV[bh] = sum_s k(s) outer v(s) ----------
// grid (64 heads, KV_SPLIT), 256 threads. Also accumulates Ksum.
__global__ void __launch_bounds__(256)
kv_kernel(const float* __restrict__ Kp, const float* __restrict__ Vp,
          float* __restrict__ KVp, float* __restrict__ KSp)
{
    const int bh = blockIdx.x;          // 0..63
    const int sp = blockIdx.y;          // 0..KV_SPLIT-1
    const int b = bh >> 4, h = bh & 15;
    const int tid = threadIdx.x;
    const int w = tid >> 5, lane = tid & 31;
    const int tx = tid & 15;            // de group
    const int ty = tid >> 4;            // dk group

    __shared__ float ks[8][64];
    __shared__ float vs[8][64];

    float acc[4][4];
#pragma unroll
    for (int i = 0; i < 4; i++)
#pragma unroll
        for (int j = 0; j < 4; j++) acc[i][j] = 0.0f;
    float kacc = 0.0f;

    const int sPer = SS / KV_SPLIT;     // 512
    const int sBase = sp * sPer;

    for (int s0 = 0; s0 < sPer; s0 += 8) {
        size_t row = ((size_t)(b * SS + sBase + s0 + w)) * DD + h * DK;
        ks[w][lane]      = Kp[row + lane];
        ks[w][lane + 32] = Kp[row + lane + 32];
        vs[w][lane]      = Vp[row + lane];
        vs[w][lane + 32] = Vp[row + lane + 32];
        __syncthreads();

        if (tid < 64) {
#pragma unroll
            for (int j = 0; j < 8; j++) kacc += ks[j][tid];
        }
#pragma unroll
        for (int j = 0; j < 8; j++) {
            float4 av = *(const float4*)&ks[j][ty * 4];
            float4 bv = *(const float4*)&vs[j][tx * 4];
            float a[4] = {av.x, av.y, av.z, av.w};
            float c[4] = {bv.x, bv.y, bv.z, bv.w};
#pragma unroll
            for (int i = 0; i < 4; i++)
#pragma unroll
                for (int jj = 0; jj < 4; jj++)
                    acc[i][jj] += a[i] * c[jj];
        }
        __syncthreads();
    }

    float* outp = KVp + ((size_t)(sp * 64 + bh)) * (DK * DK);
#pragma unroll
    for (int i = 0; i < 4; i++)
#pragma unroll
        for (int jj = 0; jj < 4; jj++)
            outp[(ty * 4 + i) * DK + tx * 4 + jj] = acc[i][jj];

    if (tid < 64)
        KSp[((size_t)(sp * 64 + bh)) * DK + tid] = kacc;
}

// ---------------- reduce KV partials -------------------------------------
__global__ void kv_reduce(const float* __restrict__ KVp, const float* __restrict__ KSp,
                          float* __restrict__ KV, float* __restrict__ KS)
{
    const int bh = blockIdx.x;
    const int tid = threadIdx.x;
    for (int e = tid; e < DK * DK; e += 256) {
        float s = 0.0f;
#pragma unroll
        for (int r = 0; r < KV_SPLIT; r++)
            s += KVp[((size_t)(r * 64 + bh)) * (DK * DK) + e];
        KV[(size_t)bh * (DK * DK) + e] = s;
    }
    if (tid < DK) {
        float s = 0.0f;
#pragma unroll
        for (int r = 0; r < KV_SPLIT; r++)
            s += KSp[((size_t)(r * 64 + bh)) * DK + tid];
        KS[(size_t)bh * DK + tid] = s;
    }
}

// ---------------- attention normalize: out = (q@KV)/(q@Ksum + eps) --------
// grid (64 heads, 32 s-chunks of 128), 256 threads
__global__ void __launch_bounds__(256)
attn_kernel(const float* __restrict__ Q, const float* __restrict__ KV,
            const float* __restrict__ KS, float* __restrict__ Aout)
{
    const int bh = blockIdx.x;
    const int sc = blockIdx.y;
    const int b = bh >> 4, h = bh & 15;
    const int tid = threadIdx.x;

    __shared__ float KVs[DK * DK];
    __shared__ float KSs[DK];
    __shared__ float qs[4][DK];

    for (int e = tid; e < DK * DK; e += 256)
        KVs[e] = KV[(size_t)bh * (DK * DK) + e];
    if (tid < DK) KSs[tid] = KS[(size_t)bh * DK + tid];
    __syncthreads();

    const int ssub = tid >> 6;   // 0..3
    const int de = tid & 63;

    for (int it = 0; it < 32; it++) {
        const int s = sc * 128 + it * 4 + ssub;
        const size_t row = ((size_t)(b * SS + s)) * DD + h * DK;
        qs[ssub][de] = Q[row + de];
        __syncthreads();

        float num = 0.0f, den = 0.0f;
#pragma unroll
        for (int dk = 0; dk < DK; dk++) {
            const float q = qs[ssub][dk];
            num += q * KVs[dk * DK + de];
            den += q * KSs[dk];
        }
        Aout[row + de] = num / (den + 1e-6f);
        __syncthreads();
    }
}

// ---------------- launch ---------------------------------------------------
extern "C" void kernel_launch(void* const* d_in, const int* in_sizes, int n_in,
                              void* d_out, int out_size)
{
    const float* query = (const float*)d_in[0];
    const float* key   = (const float*)d_in[1];
    const float* value = (const float*)d_in[2];
    const float* Wq    = (const float*)d_in[3];
    const float* Wk    = (const float*)d_in[4];
    const float* Wv    = (const float*)d_in[5];
    const float* Wo    = (const float*)d_in[6];
    const float* bo    = (const float*)d_in[7];
    float* out = (float*)d_out;

    float *gQ, *gK, *gV, *gA, *gKVp, *gKSp, *gKV, *gKS;
    cudaGetSymbolAddress((void**)&gQ,  g_Q);
    cudaGetSymbolAddress((void**)&gK,  g_K);
    cudaGetSymbolAddress((void**)&gV,  g_V);
    cudaGetSymbolAddress((void**)&gA,  g_A);
    cudaGetSymbolAddress((void**)&gKVp, g_KVp);
    cudaGetSymbolAddress((void**)&gKSp, g_KSp);
    cudaGetSymbolAddress((void**)&gKV, g_KV);
    cudaGetSymbolAddress((void**)&gKS, g_KS);

    dim3 gp(DD / BN, MM / BM);   // (8, 128)

    gemm_nt<<<gp, 256>>>(query, Wq, nullptr, gQ, MM, DD, DD, 1);  // phi
    gemm_nt<<<gp, 256>>>(key,   Wk, nullptr, gK, MM, DD, DD, 1);  // phi
    gemm_nt<<<gp, 256>>>(value, Wv, nullptr, gV, MM, DD, DD, 0);

    kv_kernel<<<dim3(64, KV_SPLIT), 256>>>(gK, gV, gKVp, gKSp);
    kv_reduce<<<64, 256>>>(gKVp, gKSp, gKV, gKS);
    attn_kernel<<<dim3(64, 32), 256>>>(gQ, gKV, gKS, gA);

    gemm_nt<<<gp, 256>>>(gA, Wo, bo, out, MM, DD, DD, 2);         // bias
}

// round 4
// speedup vs baseline: 2.0515x; 2.0515x over previous
#include <cuda_runtime.h>
#include <cuda_bf16.h>
#include <cstdint>
#include <cstddef>

// Problem constants
#define BB 4
#define SS 4096
#define DD 1024
#define HH 16
#define DK 64
#define MM (BB * SS)          // 16384

// ---------------- scratch (device globals; no runtime allocation) ----------
__device__ float g_Q[(size_t)MM * DD];
__device__ float g_K[(size_t)MM * DD];
__device__ float g_V[(size_t)MM * DD];

__device__ __nv_bfloat16 g_q_hi[(size_t)MM * DD];
__device__ __nv_bfloat16 g_q_lo[(size_t)MM * DD];
__device__ __nv_bfloat16 g_k_hi[(size_t)MM * DD];
__device__ __nv_bfloat16 g_k_lo[(size_t)MM * DD];
__device__ __nv_bfloat16 g_v_hi[(size_t)MM * DD];
__device__ __nv_bfloat16 g_v_lo[(size_t)MM * DD];
__device__ __nv_bfloat16 g_a_hi[(size_t)MM * DD];
__device__ __nv_bfloat16 g_a_lo[(size_t)MM * DD];

__device__ __nv_bfloat16 g_wq_hi[(size_t)DD * DD];
__device__ __nv_bfloat16 g_wq_lo[(size_t)DD * DD];
__device__ __nv_bfloat16 g_wk_hi[(size_t)DD * DD];
__device__ __nv_bfloat16 g_wk_lo[(size_t)DD * DD];
__device__ __nv_bfloat16 g_wv_hi[(size_t)DD * DD];
__device__ __nv_bfloat16 g_wv_lo[(size_t)DD * DD];
__device__ __nv_bfloat16 g_wo_hi[(size_t)DD * DD];
__device__ __nv_bfloat16 g_wo_lo[(size_t)DD * DD];

#define KV_SPLIT 8
__device__ float g_KVp[(size_t)KV_SPLIT * 64 * DK * DK];
__device__ float g_KSp[(size_t)KV_SPLIT * 64 * DK];
__device__ float g_KV[(size_t)64 * DK * DK];
__device__ float g_KS[(size_t)64 * DK];

// ============================ PTX helpers ==================================
__device__ __forceinline__ uint32_t s2u(const void* p) {
    uint32_t a;
    asm("{ .reg .u64 t; cvta.to.shared.u64 t, %1; cvt.u32.u64 %0, t; }"
        : "=r"(a) : "l"(p));
    return a;
}

__device__ __forceinline__ void cp16(uint32_t dst, const void* src) {
    asm volatile("cp.async.cg.shared.global [%0], [%1], 16;"
                 :: "r"(dst), "l"(src) : "memory");
}

#define LDSM4(r, addr)                                                         \
    asm volatile("ldmatrix.sync.aligned.m8n8.x4.shared.b16 "                   \
                 "{%0,%1,%2,%3}, [%4];"                                        \
                 : "=r"((r)[0]), "=r"((r)[1]), "=r"((r)[2]), "=r"((r)[3])      \
                 : "r"(addr))

#define MMA16816(d, a, b)                                                      \
    asm volatile("mma.sync.aligned.m16n8k16.row.col.f32.bf16.bf16.f32 "        \
                 "{%0,%1,%2,%3}, {%4,%5,%6,%7}, {%8,%9}, {%0,%1,%2,%3};"       \
                 : "+f"((d)[0]), "+f"((d)[1]), "+f"((d)[2]), "+f"((d)[3])      \
                 : "r"((a)[0]), "r"((a)[1]), "r"((a)[2]), "r"((a)[3]),         \
                   "r"((b)[0]), "r"((b)[1]))

// ============================ split kernel =================================
__global__ void __launch_bounds__(256)
split_fp32(const float* __restrict__ x, __nv_bfloat16* __restrict__ hi,
           __nv_bfloat16* __restrict__ lo, int n4)
{
    int i = blockIdx.x * blockDim.x + threadIdx.x;
    if (i >= n4) return;
    float4 v = ((const float4*)x)[i];
    float f[4] = {v.x, v.y, v.z, v.w};
    __nv_bfloat16 h[4], l[4];
#pragma unroll
    for (int j = 0; j < 4; j++) {
        h[j] = __float2bfloat16(f[j]);
        l[j] = __float2bfloat16(f[j] - __bfloat162float(h[j]));
    }
    __nv_bfloat162* hp = (__nv_bfloat162*)hi;
    __nv_bfloat162* lp = (__nv_bfloat162*)lo;
    hp[2 * i]     = __halves2bfloat162(h[0], h[1]);
    hp[2 * i + 1] = __halves2bfloat162(h[2], h[3]);
    lp[2 * i]     = __halves2bfloat162(l[0], l[1]);
    lp[2 * i + 1] = __halves2bfloat162(l[2], l[3]);
}

// ============================ mma.sync GEMM ================================
// C[m,n] = sum_k A[m,k]*W[n,k], fp32 via split-bf16 (hi/lo), 3 MMA products
// accumulated into ONE fp32 accumulator set.
// mode: 0 = plain, 1 = phi (elu+1), 2 = +bias
#define TM 128
#define TN 128
#define BKE 32                      // k elems per stage
#define KSTEPS (DD / BKE)           // 32
#define ROWSTRIDE 80                // bytes per smem row (40 bf16): conflict-free
#define SPLIT_B (128 * ROWSTRIDE)   // 10240
#define STAGE_B (4 * SPLIT_B)       // 40960 (Ah, Al, Bh, Bl)
#define NSTAGE 3
#define GSMEM (NSTAGE * STAGE_B)    // 122880

__global__ void __launch_bounds__(256)
gemm_mma(const __nv_bfloat16* __restrict__ Ahi, const __nv_bfloat16* __restrict__ Alo,
         const __nv_bfloat16* __restrict__ Bhi, const __nv_bfloat16* __restrict__ Blo,
         const float* __restrict__ bias, float* __restrict__ C, int mode)
{
    extern __shared__ char smem[];
    const uint32_t sb = s2u(smem);
    const int tid = threadIdx.x;
    const int lane = tid & 31;
    const int warp = tid >> 5;
    const int wm = warp & 3;        // 32-row slab
    const int wn = warp >> 2;       // 64-col slab
    const int bm = blockIdx.y * TM;
    const int bn = blockIdx.x * TN;

    const __nv_bfloat16* gsrc[4];
    gsrc[0] = Ahi + (size_t)bm * DD;
    gsrc[1] = Alo + (size_t)bm * DD;
    gsrc[2] = Bhi + (size_t)bn * DD;
    gsrc[3] = Blo + (size_t)bn * DD;

    const int lrow = tid >> 2;      // 0..63
    const int lch  = tid & 3;       // 16B chunk within 64B k-row

    auto produce = [&](int c) {
        const uint32_t st = sb + (uint32_t)(c % NSTAGE) * STAGE_B;
#pragma unroll
        for (int s = 0; s < 4; s++) {
#pragma unroll
            for (int it = 0; it < 2; it++) {
                const int r = lrow + it * 64;
                const __nv_bfloat16* g = gsrc[s] + (size_t)r * DD + c * BKE + lch * 8;
                cp16(st + (uint32_t)(s * SPLIT_B + r * ROWSTRIDE + lch * 16), g);
            }
        }
        asm volatile("cp.async.commit_group;" ::: "memory");
    };

    float acc[2][8][4];
#pragma unroll
    for (int i = 0; i < 2; i++)
#pragma unroll
        for (int j = 0; j < 8; j++)
#pragma unroll
            for (int k = 0; k < 4; k++) acc[i][j][k] = 0.0f;

    produce(0);
    produce(1);

    for (int c = 0; c < KSTEPS; c++) {
        if (c == KSTEPS - 1)
            asm volatile("cp.async.wait_group 0;" ::: "memory");
        else
            asm volatile("cp.async.wait_group 1;" ::: "memory");
        __syncthreads();

        const uint32_t st = sb + (uint32_t)(c % NSTAGE) * STAGE_B;
#pragma unroll
        for (int step = 0; step < 2; step++) {
            uint32_t ah[2][4], al[2][4], bh[8][2], bl[8][2];
#pragma unroll
            for (int mt = 0; mt < 2; mt++) {
                const int row = wm * 32 + mt * 16 + (lane & 15);
                const uint32_t off =
                    (uint32_t)(row * ROWSTRIDE + step * 32 + ((lane >> 4) & 1) * 16);
                LDSM4(ah[mt], st + off);
                LDSM4(al[mt], st + SPLIT_B + off);
            }
#pragma unroll
            for (int nt2 = 0; nt2 < 4; nt2++) {
                // B tile is [N,K] row-major (k contiguous) == same structure as A
                // -> NON-trans ldmatrix yields the required col-fragment.
                const int nrow = wn * 64 + nt2 * 16 + (lane & 7) + ((lane >> 4) & 1) * 8;
                const uint32_t off =
                    (uint32_t)(nrow * ROWSTRIDE + step * 32 + ((lane >> 3) & 1) * 16);
                uint32_t r[4];
                LDSM4(r, st + 2 * SPLIT_B + off);
                bh[nt2 * 2][0] = r[0]; bh[nt2 * 2][1] = r[1];
                bh[nt2 * 2 + 1][0] = r[2]; bh[nt2 * 2 + 1][1] = r[3];
                LDSM4(r, st + 3 * SPLIT_B + off);
                bl[nt2 * 2][0] = r[0]; bl[nt2 * 2][1] = r[1];
                bl[nt2 * 2 + 1][0] = r[2]; bl[nt2 * 2 + 1][1] = r[3];
            }
#pragma unroll
            for (int mt = 0; mt < 2; mt++)
#pragma unroll
                for (int nt = 0; nt < 8; nt++) {
                    MMA16816(acc[mt][nt], ah[mt], bh[nt]);
                    MMA16816(acc[mt][nt], ah[mt], bl[nt]);
                    MMA16816(acc[mt][nt], al[mt], bh[nt]);
                }
        }
        if (c + 2 < KSTEPS) produce(c + 2);
    }

    // epilogue
    const int gr = lane >> 2;        // 0..7
    const int gc = (lane & 3) * 2;   // 0,2,4,6
#pragma unroll
    for (int mt = 0; mt < 2; mt++) {
#pragma unroll
        for (int nt = 0; nt < 8; nt++) {
            const int row0 = bm + wm * 32 + mt * 16 + gr;
            const int col  = bn + wn * 64 + nt * 8 + gc;
            float v[4] = {acc[mt][nt][0], acc[mt][nt][1],
                          acc[mt][nt][2], acc[mt][nt][3]};
            if (mode == 1) {
#pragma unroll
                for (int j = 0; j < 4; j++)
                    v[j] = (v[j] > 0.0f) ? (v[j] + 1.0f) : expf(v[j]);
            } else if (mode == 2) {
                const float b0 = bias[col], b1 = bias[col + 1];
                v[0] += b0; v[1] += b1; v[2] += b0; v[3] += b1;
            }
            float2 p0; p0.x = v[0]; p0.y = v[1];
            float2 p1; p1.x = v[2]; p1.y = v[3];
            *(float2*)(C + (size_t)row0 * DD + col) = p0;
            *(float2*)(C + (size_t)(row0 + 8) * DD + col) = p1;
        }
    }
}

// ---------------- KV accumulation: KV[bh] = sum_s k(s) outer v(s) ----------
__global__ void __launch_bounds__(256)
kv_kernel(const float* __restrict__ Kp, const float* __restrict__ Vp,
          float* __restrict__ KVp, float* __restrict__ KSp)
{
    const int bh = blockIdx.x;          // 0..63
    const int sp = blockIdx.y;          // 0..KV_SPLIT-1
    const int b = bh >> 4, h = bh & 15;
    const int tid = threadIdx.x;
    const int w = tid >> 5, lane = tid & 31;
    const int tx = tid & 15;
    const int ty = tid >> 4;

    __shared__ float ks[8][64];
    __shared__ float vs[8][64];

    float acc[4][4];
#pragma unroll
    for (int i = 0; i < 4; i++)
#pragma unroll
        for (int j = 0; j < 4; j++) acc[i][j] = 0.0f;
    float kacc = 0.0f;

    const int sPer = SS / KV_SPLIT;
    const int sBase = sp * sPer;

    for (int s0 = 0; s0 < sPer; s0 += 8) {
        size_t row = ((size_t)(b * SS + sBase + s0 + w)) * DD + h * DK;
        ks[w][lane]      = Kp[row + lane];
        ks[w][lane + 32] = Kp[row + lane + 32];
        vs[w][lane]      = Vp[row + lane];
        vs[w][lane + 32] = Vp[row + lane + 32];
        __syncthreads();

        if (tid < 64) {
#pragma unroll
            for (int j = 0; j < 8; j++) kacc += ks[j][tid];
        }
#pragma unroll
        for (int j = 0; j < 8; j++) {
            float4 av = *(const float4*)&ks[j][ty * 4];
            float4 bv = *(const float4*)&vs[j][tx * 4];
            float a[4] = {av.x, av.y, av.z, av.w};
            float c[4] = {bv.x, bv.y, bv.z, bv.w};
#pragma unroll
            for (int i = 0; i < 4; i++)
#pragma unroll
                for (int jj = 0; jj < 4; jj++)
                    acc[i][jj] += a[i] * c[jj];
        }
        __syncthreads();
    }

    float* outp = KVp + ((size_t)(sp * 64 + bh)) * (DK * DK);
#pragma unroll
    for (int i = 0; i < 4; i++)
#pragma unroll
        for (int jj = 0; jj < 4; jj++)
            outp[(ty * 4 + i) * DK + tx * 4 + jj] = acc[i][jj];

    if (tid < 64)
        KSp[((size_t)(sp * 64 + bh)) * DK + tid] = kacc;
}

__global__ void kv_reduce(const float* __restrict__ KVp, const float* __restrict__ KSp,
                          float* __restrict__ KV, float* __restrict__ KS)
{
    const int bh = blockIdx.x;
    const int tid = threadIdx.x;
    for (int e = tid; e < DK * DK; e += 256) {
        float s = 0.0f;
#pragma unroll
        for (int r = 0; r < KV_SPLIT; r++)
            s += KVp[((size_t)(r * 64 + bh)) * (DK * DK) + e];
        KV[(size_t)bh * (DK * DK) + e] = s;
    }
    if (tid < DK) {
        float s = 0.0f;
#pragma unroll
        for (int r = 0; r < KV_SPLIT; r++)
            s += KSp[((size_t)(r * 64 + bh)) * DK + tid];
        KS[(size_t)bh * DK + tid] = s;
    }
}

// ---------------- attention normalize -> split-bf16 output -----------------
__global__ void __launch_bounds__(256)
attn_kernel(const float* __restrict__ Q, const float* __restrict__ KV,
            const float* __restrict__ KS,
            __nv_bfloat16* __restrict__ Ahi, __nv_bfloat16* __restrict__ Alo)
{
    const int bh = blockIdx.x;
    const int sc = blockIdx.y;
    const int b = bh >> 4, h = bh & 15;
    const int tid = threadIdx.x;

    __shared__ float KVs[DK * DK];
    __shared__ float KSs[DK];
    __shared__ float qs[4][DK];

    for (int e = tid; e < DK * DK; e += 256)
        KVs[e] = KV[(size_t)bh * (DK * DK) + e];
    if (tid < DK) KSs[tid] = KS[(size_t)bh * DK + tid];
    __syncthreads();

    const int ssub = tid >> 6;
    const int de = tid & 63;

    for (int it = 0; it < 32; it++) {
        const int s = sc * 128 + it * 4 + ssub;
        const size_t row = ((size_t)(b * SS + s)) * DD + h * DK;
        qs[ssub][de] = Q[row + de];
        __syncthreads();

        float num = 0.0f, den = 0.0f;
#pragma unroll
        for (int dk = 0; dk < DK; dk++) {
            const float q = qs[ssub][dk];
            num += q * KVs[dk * DK + de];
            den += q * KSs[dk];
        }
        float o = num / (den + 1e-6f);
        __nv_bfloat16 hv = __float2bfloat16(o);
        Ahi[row + de] = hv;
        Alo[row + de] = __float2bfloat16(o - __bfloat162float(hv));
        __syncthreads();
    }
}

// ---------------- launch ---------------------------------------------------
extern "C" void kernel_launch(void* const* d_in, const int* in_sizes, int n_in,
                              void* d_out, int out_size)
{
    const float* query = (const float*)d_in[0];
    const float* key   = (const float*)d_in[1];
    const float* value = (const float*)d_in[2];
    const float* Wq    = (const float*)d_in[3];
    const float* Wk    = (const float*)d_in[4];
    const float* Wv    = (const float*)d_in[5];
    const float* Wo    = (const float*)d_in[6];
    const float* bo    = (const float*)d_in[7];
    float* out = (float*)d_out;

    float *gQ, *gK, *gV, *gKVp, *gKSp, *gKV, *gKS;
    __nv_bfloat16 *qh, *ql, *kh, *kl, *vh, *vl, *ah, *al;
    __nv_bfloat16 *wqh, *wql, *wkh, *wkl, *wvh, *wvl, *woh, *wol;
    cudaGetSymbolAddress((void**)&gQ,  g_Q);
    cudaGetSymbolAddress((void**)&gK,  g_K);
    cudaGetSymbolAddress((void**)&gV,  g_V);
    cudaGetSymbolAddress((void**)&gKVp, g_KVp);
    cudaGetSymbolAddress((void**)&gKSp, g_KSp);
    cudaGetSymbolAddress((void**)&gKV, g_KV);
    cudaGetSymbolAddress((void**)&gKS, g_KS);
    cudaGetSymbolAddress((void**)&qh, g_q_hi);
    cudaGetSymbolAddress((void**)&ql, g_q_lo);
    cudaGetSymbolAddress((void**)&kh, g_k_hi);
    cudaGetSymbolAddress((void**)&kl, g_k_lo);
    cudaGetSymbolAddress((void**)&vh, g_v_hi);
    cudaGetSymbolAddress((void**)&vl, g_v_lo);
    cudaGetSymbolAddress((void**)&ah, g_a_hi);
    cudaGetSymbolAddress((void**)&al, g_a_lo);
    cudaGetSymbolAddress((void**)&wqh, g_wq_hi);
    cudaGetSymbolAddress((void**)&wql, g_wq_lo);
    cudaGetSymbolAddress((void**)&wkh, g_wk_hi);
    cudaGetSymbolAddress((void**)&wkl, g_wk_lo);
    cudaGetSymbolAddress((void**)&wvh, g_wv_hi);
    cudaGetSymbolAddress((void**)&wvl, g_wv_lo);
    cudaGetSymbolAddress((void**)&woh, g_wo_hi);
    cudaGetSymbolAddress((void**)&wol, g_wo_lo);

    cudaFuncSetAttribute(gemm_mma, cudaFuncAttributeMaxDynamicSharedMemorySize,
                         GSMEM);

    const int nAct4 = (MM * DD) / 4;
    const int nW4   = (DD * DD) / 4;
    split_fp32<<<nAct4 / 256, 256>>>(query, qh, ql, nAct4);
    split_fp32<<<nAct4 / 256, 256>>>(key,   kh, kl, nAct4);
    split_fp32<<<nAct4 / 256, 256>>>(value, vh, vl, nAct4);
    split_fp32<<<nW4 / 256, 256>>>(Wq, wqh, wql, nW4);
    split_fp32<<<nW4 / 256, 256>>>(Wk, wkh, wkl, nW4);
    split_fp32<<<nW4 / 256, 256>>>(Wv, wvh, wvl, nW4);
    split_fp32<<<nW4 / 256, 256>>>(Wo, woh, wol, nW4);

    dim3 gg(DD / TN, MM / TM);   // (8, 128)
    gemm_mma<<<gg, 256, GSMEM>>>(qh, ql, wqh, wql, nullptr, gQ, 1);  // phi
    gemm_mma<<<gg, 256, GSMEM>>>(kh, kl, wkh, wkl, nullptr, gK, 1);  // phi
    gemm_mma<<<gg, 256, GSMEM>>>(vh, vl, wvh, wvl, nullptr, gV, 0);

    kv_kernel<<<dim3(64, KV_SPLIT), 256>>>(gK, gV, gKVp, gKSp);
    kv_reduce<<<64, 256>>>(gKVp, gKSp, gKV, gKS);
    attn_kernel<<<dim3(64, 32), 256>>>(gQ, gKV, gKS, ah, al);

    gemm_mma<<<gg, 256, GSMEM>>>(ah, al, woh, wol, bo, out, 2);      // bias
}